// round 14
// baseline (speedup 1.0000x reference)
#include <cuda_runtime.h>
#include <cuda_fp16.h>
#include <cstdint>

#define BB   4
#define CC   512
#define NSEQ 4096
#define DQK  64
#define LOG2E 1.4426950408889634f

// ---------------- scratch (static device globals: allocation-free) ----------
__device__ __half g_qh[BB * NSEQ * DQK];            // [b][i][d] hi
__device__ __half g_ql[BB * NSEQ * DQK];            // [b][i][d] lo
__device__ __half g_kh[BB * NSEQ * DQK];            // [b][j][d] hi
__device__ __half g_kl[BB * NSEQ * DQK];            // [b][j][d] lo
__device__ __half g_v [(size_t)BB * CC * NSEQ];     // [b][c][j] single fp16

__device__ __forceinline__ float ex2f(float x) {
    float r; asm("ex2.approx.f32 %0, %1;" : "=f"(r) : "f"(x)); return r;
}
__device__ __forceinline__ uint32_t smem_u32(const void* p) {
    uint32_t a;
    asm("{ .reg .u64 t; cvta.to.shared.u64 t, %1; cvt.u32.u64 %0, t; }" : "=r"(a) : "l"(p));
    return a;
}
__device__ __forceinline__ uint32_t pack_h2(float a, float b) {
    __half2 h = __floats2half2_rn(a, b);
    return *(uint32_t*)&h;
}
__device__ __forceinline__ uint32_t h2mul(uint32_t a, uint32_t b) {
    uint32_t r;
    asm("mul.rn.f16x2 %0, %1, %2;" : "=r"(r) : "r"(a), "r"(b));
    return r;
}
__device__ __forceinline__ void mma_f16(float* c, const uint32_t* a, uint32_t b0, uint32_t b1) {
    asm volatile("mma.sync.aligned.m16n8k16.row.col.f32.f16.f16.f32 "
        "{%0,%1,%2,%3}, {%4,%5,%6,%7}, {%8,%9}, {%0,%1,%2,%3};"
        : "+f"(c[0]), "+f"(c[1]), "+f"(c[2]), "+f"(c[3])
        : "r"(a[0]), "r"(a[1]), "r"(a[2]), "r"(a[3]), "r"(b0), "r"(b1));
}
__device__ __forceinline__ void ldsm4(uint32_t* r, uint32_t a) {
    asm volatile("ldmatrix.sync.aligned.m8n8.x4.shared.b16 {%0,%1,%2,%3}, [%4];"
        : "=r"(r[0]), "=r"(r[1]), "=r"(r[2]), "=r"(r[3]) : "r"(a));
}
__device__ __forceinline__ void cp16(uint32_t dst, const void* src) {
    asm volatile("cp.async.cg.shared.global [%0], [%1], 16;" :: "r"(dst), "l"(src));
}
#define CP_COMMIT() asm volatile("cp.async.commit_group;" ::: "memory")
#define CP_WAIT1()  asm volatile("cp.async.wait_group 1;" ::: "memory")
__device__ __forceinline__ void sts32(uint32_t a, uint32_t v) {
    asm volatile("st.shared.b32 [%0], %1;" :: "r"(a), "r"(v) : "memory");
}
__device__ __forceinline__ float lds32f(uint32_t a) {
    float v; asm volatile("ld.shared.f32 %0, [%1];" : "=f"(v) : "r"(a)); return v;
}
__device__ __forceinline__ void sts32f(uint32_t a, float v) {
    asm volatile("st.shared.f32 [%0], %1;" :: "r"(a), "f"(v) : "memory");
}

// ---------------- pass 1: QKV projection (SIMT fp32, 128x128 tile) ----------
#define PW 140
#define PX 132

__global__ __launch_bounds__(256) void proj_kernel(
    const float* __restrict__ x,
    const float* __restrict__ wq, const float* __restrict__ bq,
    const float* __restrict__ wk, const float* __restrict__ bk,
    const float* __restrict__ wv, const float* __restrict__ bv)
{
    __shared__ float ws[16][PW];
    __shared__ float xs[16][PX];

    const int b  = blockIdx.z;
    const int o0 = blockIdx.y * 128;
    const int n0 = blockIdx.x * 128;
    const int t  = threadIdx.x;
    const int tx = t & 15;
    const int ty = t >> 4;

    const float* wptr[2];
    int wrow[2];
    const int wc4 = (t & 3) * 4;
#pragma unroll
    for (int r = 0; r < 2; r++) {
        int row = r * 64 + (t >> 2);
        wrow[r] = row;
        int o = o0 + row;
        const float* base;
        if (o < 64)        base = wq + (size_t)o * CC;
        else if (o < 128)  base = wk + (size_t)(o - 64) * CC;
        else               base = wv + (size_t)(o - 128) * CC;
        wptr[r] = base + wc4;
    }
    const int xn4 = (t & 31) * 4;
    const float* xptr[2];
    int xcr[2];
#pragma unroll
    for (int r = 0; r < 2; r++) {
        int c = r * 8 + (t >> 5);
        xcr[r] = c;
        xptr[r] = x + ((size_t)(b * CC) + c) * NSEQ + n0 + xn4;
    }

    float acc[8][8];
#pragma unroll
    for (int i = 0; i < 8; i++)
#pragma unroll
        for (int j = 0; j < 8; j++) acc[i][j] = 0.f;

    for (int c0 = 0; c0 < CC; c0 += 16) {
        float4 w4[2], x4[2];
#pragma unroll
        for (int r = 0; r < 2; r++) {
            w4[r] = *(const float4*)(wptr[r] + c0);
            x4[r] = *(const float4*)(xptr[r] + (size_t)c0 * NSEQ);
        }
        __syncthreads();
#pragma unroll
        for (int r = 0; r < 2; r++) {
            ws[wc4 + 0][wrow[r]] = w4[r].x;
            ws[wc4 + 1][wrow[r]] = w4[r].y;
            ws[wc4 + 2][wrow[r]] = w4[r].z;
            ws[wc4 + 3][wrow[r]] = w4[r].w;
            *(float4*)&xs[xcr[r]][xn4] = x4[r];
        }
        __syncthreads();
#pragma unroll
        for (int c = 0; c < 16; c++) {
            float4 a0 = *(const float4*)&ws[c][4 * ty];
            float4 a1 = *(const float4*)&ws[c][4 * ty + 64];
            float4 b0 = *(const float4*)&xs[c][4 * tx];
            float4 b1 = *(const float4*)&xs[c][4 * tx + 64];
            float av[8] = {a0.x, a0.y, a0.z, a0.w, a1.x, a1.y, a1.z, a1.w};
            float bv2[8] = {b0.x, b0.y, b0.z, b0.w, b1.x, b1.y, b1.z, b1.w};
#pragma unroll
            for (int i = 0; i < 8; i++)
#pragma unroll
                for (int j = 0; j < 8; j++)
                    acc[i][j] = fmaf(av[i], bv2[j], acc[i][j]);
        }
    }

    if (blockIdx.y == 0) {
#pragma unroll
        for (int i = 0; i < 8; i++) {
            int o = 4 * ty + (i >> 2) * 64 + (i & 3);
            int d = o & 63;
            float bias = (o < 64) ? bq[d] : bk[d];
            __half* dh = ((o < 64) ? g_qh : g_kh) + (size_t)(b * NSEQ) * DQK + d;
            __half* dl = ((o < 64) ? g_ql : g_kl) + (size_t)(b * NSEQ) * DQK + d;
#pragma unroll
            for (int j = 0; j < 8; j++) {
                int n = n0 + 4 * tx + (j >> 2) * 64 + (j & 3);
                float v = acc[i][j] + bias;
                __half h = __float2half_rn(v);
                __half l = __float2half_rn(v - __half2float(h));
                dh[(size_t)n * DQK] = h;
                dl[(size_t)n * DQK] = l;
            }
        }
    } else {
#pragma unroll
        for (int i = 0; i < 8; i++) {
            int c = (blockIdx.y - 1) * 128 + 4 * ty + (i >> 2) * 64 + (i & 3);
            float bias = bv[c];
#pragma unroll
            for (int k = 0; k < 2; k++) {
                int n = n0 + 4 * tx + k * 64;
                uint2 w2;
                w2.x = pack_h2(acc[i][4 * k + 0] + bias, acc[i][4 * k + 1] + bias);
                w2.y = pack_h2(acc[i][4 * k + 2] + bias, acc[i][4 * k + 3] + bias);
                *(uint2*)&g_v[((size_t)(b * CC + c)) * NSEQ + n] = w2;
            }
        }
    }
}

// ---------------- pass 2: HMMA flash attention, low-reg 64i x 256c ----------
// 256 thr, 8 warps = (iw 0..1: 32 i rows) x (q 0..3: j-quarter / 64c group).
// GEMM1: warp 32i x 16j (split-3). P exchanged via SMEM (own-frame fp16),
// per-quarter correction. GEMM2: warp 32i x 64c -> o = 64 regs (no spills).
#define KROW   144
#define S_Q    0                     /* Q hi 9216 | lo 9216 */
#define S_P    18432                 /* P: 64 x 144 */
#define S_MX   27648                 /* chunk max: 4 quarters x 64 rows x 4B */
#define S_BUF  28672
#define SK_H   0
#define SK_L   9216
#define SV     18432
#define TILE_BYTES 55296             /* K 2x9216 + V 256x144 */
#define N_CHUNK (NSEQ / 64)
#define STG_ROW 68
#define OUT_SMEM_BYTES (S_BUF + 2 * TILE_BYTES)   /* 139264 */

__device__ __forceinline__ void issue_tiles(uint32_t tb, int b, int j0, int c0, int t)
{
#pragma unroll
    for (int r = 0; r < 4; r++) {           // K hi+lo: 1024 16B chunks
        int idx = t + r * 256;
        int arr = idx >> 9;
        int row = (idx >> 3) & 63;
        int col = idx & 7;
        const __half* src = (arr ? g_kl : g_kh) + ((size_t)b * NSEQ + j0 + row) * DQK + col * 8;
        cp16(tb + SK_H + arr * 9216 + row * KROW + col * 16, src);
    }
#pragma unroll
    for (int r = 0; r < 8; r++) {           // V: 2048 16B chunks (256 c rows)
        int idx = t + r * 256;
        int row = (idx >> 3) & 255;
        int col = idx & 7;
        const __half* src = g_v + ((size_t)(b * CC + c0 + row)) * NSEQ + j0 + col * 8;
        cp16(tb + SV + row * KROW + col * 16, src);
    }
}

__global__ __launch_bounds__(256, 1) void out_kernel(float* __restrict__ out)
{
    extern __shared__ char smem[];
    const uint32_t sb = smem_u32(smem);
    const int b  = blockIdx.z;
    const int i0 = blockIdx.x * 64;
    const int c0 = blockIdx.y * 256;
    const int t  = threadIdx.x;
    const int w  = t >> 5;
    const int lane = t & 31;
    const int g  = lane >> 2;
    const int t4 = lane & 3;
    const int l8 = lane & 7;
    const int tt = lane >> 3;
    const int iw = w & 1;        // 32-i group
    const int q  = w >> 1;       // j-quarter (GEMM1) == c-quarter (GEMM2)

    // stage Q hi/lo [64 i][64 d]
#pragma unroll
    for (int r = 0; r < 4; r++) {
        int idx = t + r * 256;
        int arr = idx >> 9;
        int row = (idx >> 3) & 63;
        int col = idx & 7;
        const __half* src = (arr ? g_ql : g_qh) + ((size_t)b * NSEQ + i0 + row) * DQK + col * 8;
        cp16(sb + S_Q + arr * 9216 + row * KROW + col * 16, src);
    }
    issue_tiles(sb + S_BUF, b, 0, c0, t);
    CP_COMMIT();

    // per-m fragment row bases
    uint32_t fr[2], psA[2], mrow[2];
#pragma unroll
    for (int m = 0; m < 2; m++) {
        int rbase = iw * 32 + m * 16;
        fr[m]   = (uint32_t)(rbase + l8 + ((lane >> 3) & 1) * 8) * KROW
                + (uint32_t)((lane >> 4) * 16);
        psA[m]  = sb + S_P + (uint32_t)(rbase + g) * KROW + (uint32_t)(q * 32 + 4 * t4);
        mrow[m] = sb + S_MX + (uint32_t)(rbase + g) * 4;
    }

    float o[2][8][4];
#pragma unroll
    for (int m = 0; m < 2; m++)
#pragma unroll
        for (int nt = 0; nt < 8; nt++)
#pragma unroll
            for (int r = 0; r < 4; r++) o[m][nt][r] = 0.f;
    float la[2][4] = {{0.f, 0.f, 0.f, 0.f}, {0.f, 0.f, 0.f, 0.f}};
    float mr[2][2] = {{-1e30f, -1e30f}, {-1e30f, -1e30f}};
    const uint32_t ONE2 = 0x3C003C00u;

    for (int it = 0; it < N_CHUNK; ++it) {
        if (it + 1 < N_CHUNK)
            issue_tiles(sb + S_BUF + ((it + 1) & 1) * TILE_BYTES, b, (it + 1) * 64, c0, t);
        CP_COMMIT();
        CP_WAIT1();
        __syncthreads();

        const uint32_t tb = sb + S_BUF + (it & 1) * TILE_BYTES;

        // ---- GEMM1: S = Q K^T, warp = 32i x 16j (split-3 fp16) ----
        float s[2][2][4];
#pragma unroll
        for (int m = 0; m < 2; m++)
#pragma unroll
            for (int nt = 0; nt < 2; nt++)
#pragma unroll
                for (int r = 0; r < 4; r++) s[m][nt][r] = 0.f;

#pragma unroll
        for (int kp = 0; kp < 2; kp++) {
            uint32_t qh[2][8];  // per m: qh0(4), qh1(4) packed; lo in ql
            uint32_t ql[2][8];
#pragma unroll
            for (int m = 0; m < 2; m++) {
                uint32_t base = sb + S_Q + fr[m] + (uint32_t)(kp * 64);
                ldsm4(&qh[m][0], base);
                ldsm4(&qh[m][4], base + 32);
                ldsm4(&ql[m][0], base + 9216);
                ldsm4(&ql[m][4], base + 9216 + 32);
            }
#pragma unroll
            for (int nt = 0; nt < 2; nt++) {
                uint32_t krow = tb + (q * 16 + nt * 8 + l8) * KROW + tt * 16;
                uint32_t kh[4], kl[4];
                ldsm4(kh, krow + SK_H + kp * 64);
                ldsm4(kl, krow + SK_L + kp * 64);
#pragma unroll
                for (int m = 0; m < 2; m++) {
                    mma_f16(s[m][nt], &qh[m][0], kh[0], kh[1]);
                    mma_f16(s[m][nt], &qh[m][4], kh[2], kh[3]);
                    mma_f16(s[m][nt], &ql[m][0], kh[0], kh[1]);
                    mma_f16(s[m][nt], &ql[m][4], kh[2], kh[3]);
                    mma_f16(s[m][nt], &qh[m][0], kl[0], kl[1]);
                    mma_f16(s[m][nt], &qh[m][4], kl[2], kl[3]);
                }
            }
        }

        // ---- own-quarter chunk max + own-frame exp + STS P ----
        float cmL[2][2];
#pragma unroll
        for (int m = 0; m < 2; m++) {
            float cm0 = fmaxf(fmaxf(s[m][0][0], s[m][0][1]), fmaxf(s[m][1][0], s[m][1][1]));
            float cm1 = fmaxf(fmaxf(s[m][0][2], s[m][0][3]), fmaxf(s[m][1][2], s[m][1][3]));
            cm0 = fmaxf(cm0, __shfl_xor_sync(0xFFFFFFFFu, cm0, 1));
            cm0 = fmaxf(cm0, __shfl_xor_sync(0xFFFFFFFFu, cm0, 2));
            cm1 = fmaxf(cm1, __shfl_xor_sync(0xFFFFFFFFu, cm1, 1));
            cm1 = fmaxf(cm1, __shfl_xor_sync(0xFFFFFFFFu, cm1, 2));
            cmL[m][0] = cm0 * LOG2E;
            cmL[m][1] = cm1 * LOG2E;
            if (t4 == 0) {
                sts32f(mrow[m] + (uint32_t)(q * 256), cmL[m][0]);
                sts32f(mrow[m] + (uint32_t)(q * 256) + 32, cmL[m][1]);
            }
#pragma unroll
            for (int nt = 0; nt < 2; nt++) {
                float p0 = ex2f(fmaf(s[m][nt][0], LOG2E, -cmL[m][0]));
                float p1 = ex2f(fmaf(s[m][nt][1], LOG2E, -cmL[m][0]));
                float p2 = ex2f(fmaf(s[m][nt][2], LOG2E, -cmL[m][1]));
                float p3 = ex2f(fmaf(s[m][nt][3], LOG2E, -cmL[m][1]));
                sts32(psA[m] + nt * 16, pack_h2(p0, p1));
                sts32(psA[m] + 8 * KROW + nt * 16, pack_h2(p2, p3));
            }
        }
        __syncthreads();

        // ---- global frame + corrections + P fragments + row sums ----
        uint32_t pa[2][4][4];
        float f[2][2];
#pragma unroll
        for (int m = 0; m < 2; m++) {
            float hq0[4], hq1[4];
#pragma unroll
            for (int qq = 0; qq < 4; qq++) {
                hq0[qq] = lds32f(mrow[m] + (uint32_t)(qq * 256));
                hq1[qq] = lds32f(mrow[m] + (uint32_t)(qq * 256) + 32);
            }
            float m0n = fmaxf(fmaxf(mr[m][0], fmaxf(hq0[0], hq0[1])), fmaxf(hq0[2], hq0[3]));
            float m1n = fmaxf(fmaxf(mr[m][1], fmaxf(hq1[0], hq1[1])), fmaxf(hq1[2], hq1[3]));
            f[m][0] = ex2f(mr[m][0] - m0n);
            f[m][1] = ex2f(mr[m][1] - m1n);
            mr[m][0] = m0n; mr[m][1] = m1n;
            la[m][0] *= f[m][0]; la[m][1] *= f[m][0];
            la[m][2] *= f[m][1]; la[m][3] *= f[m][1];
#pragma unroll
            for (int kt = 0; kt < 4; kt++)
                ldsm4(pa[m][kt], sb + S_P + fr[m] + kt * 32);
#pragma unroll
            for (int kt = 0; kt < 4; kt++) {
                float e0 = ex2f(hq0[kt] - m0n);
                float e1 = ex2f(hq1[kt] - m1n);
                const uint32_t cr0 = pack_h2(e0, e0);
                const uint32_t cr1 = pack_h2(e1, e1);
                pa[m][kt][0] = h2mul(pa[m][kt][0], cr0);
                pa[m][kt][1] = h2mul(pa[m][kt][1], cr1);
                pa[m][kt][2] = h2mul(pa[m][kt][2], cr0);
                pa[m][kt][3] = h2mul(pa[m][kt][3], cr1);
            }
#pragma unroll
            for (int kt = 0; kt < 4; kt++)
                mma_f16(la[m], pa[m][kt], ONE2, ONE2);
        }
        // rescale o to new frame
        if (__any_sync(0xFFFFFFFFu,
                fminf(fminf(f[0][0], f[0][1]), fminf(f[1][0], f[1][1])) < 0.9999995f)) {
#pragma unroll
            for (int m = 0; m < 2; m++)
#pragma unroll
                for (int nt = 0; nt < 8; nt++) {
                    o[m][nt][0] *= f[m][0]; o[m][nt][1] *= f[m][0];
                    o[m][nt][2] *= f[m][1]; o[m][nt][3] *= f[m][1];
                }
        }

        // ---- GEMM2: o += P V^T, warp tile 32i x 64c ----
#pragma unroll
        for (int nt = 0; nt < 8; nt++) {
            uint32_t vrow = tb + SV + (q * 64 + nt * 8 + l8) * KROW + tt * 16;
#pragma unroll
            for (int jh = 0; jh < 2; jh++) {
                uint32_t vv[4];
                ldsm4(vv, vrow + jh * 64);
                mma_f16(o[0][nt], pa[0][2 * jh],     vv[0], vv[1]);
                mma_f16(o[0][nt], pa[0][2 * jh + 1], vv[2], vv[3]);
                mma_f16(o[1][nt], pa[1][2 * jh],     vv[0], vv[1]);
                mma_f16(o[1][nt], pa[1][2 * jh + 1], vv[2], vv[3]);
            }
        }
        __syncthreads();
    }

    float li[2][2];
#pragma unroll
    for (int m = 0; m < 2; m++) {
        li[m][0] = 1.0f / la[m][0];
        li[m][1] = 1.0f / la[m][2];
    }

    // epilogue: scale, transpose through SMEM staging (256c x 64i), store
    float* stg = (float*)smem;
#pragma unroll
    for (int m = 0; m < 2; m++) {
        const int il = iw * 32 + m * 16 + g;
#pragma unroll
        for (int nt = 0; nt < 8; nt++) {
            int c = q * 64 + nt * 8 + 2 * t4;
            stg[(size_t)c * STG_ROW + il]           = o[m][nt][0] * li[m][0];
            stg[(size_t)(c + 1) * STG_ROW + il]     = o[m][nt][1] * li[m][0];
            stg[(size_t)c * STG_ROW + il + 8]       = o[m][nt][2] * li[m][1];
            stg[(size_t)(c + 1) * STG_ROW + il + 8] = o[m][nt][3] * li[m][1];
        }
    }
    __syncthreads();
#pragma unroll
    for (int r = 0; r < 16; r++) {
        int fid = t + r * 256;               // 4096 float4 = 256c x 16
        int c = fid >> 4, x = fid & 15;
        float4 v = *(const float4*)&stg[(size_t)c * STG_ROW + x * 4];
        *(float4*)(out + ((size_t)(b * CC + c0 + c)) * NSEQ + i0 + x * 4) = v;
    }
}

// ---------------- launch ----------------------------------------------------
extern "C" void kernel_launch(void* const* d_in, const int* in_sizes, int n_in,
                              void* d_out, int out_size)
{
    const float* x  = (const float*)d_in[0];
    const float* wq = (const float*)d_in[1];
    const float* bq = (const float*)d_in[2];
    const float* wk = (const float*)d_in[3];
    const float* bk = (const float*)d_in[4];
    const float* wv = (const float*)d_in[5];
    const float* bv = (const float*)d_in[6];
    float* out = (float*)d_out;

    proj_kernel<<<dim3(NSEQ / 128, 5, BB), 256>>>(x, wq, bq, wk, bk, wv, bv);
    cudaFuncSetAttribute(out_kernel, cudaFuncAttributeMaxDynamicSharedMemorySize, OUT_SMEM_BYTES);
    out_kernel<<<dim3(NSEQ / 64, CC / 256, BB), 256, OUT_SMEM_BYTES>>>(out);
}

// round 15
// speedup vs baseline: 1.3280x; 1.3280x over previous
#include <cuda_runtime.h>
#include <cuda_fp16.h>
#include <cstdint>

#define BB   4
#define CC   512
#define NSEQ 4096
#define DQK  64
#define LOG2E 1.4426950408889634f

// ---------------- scratch (static device globals: allocation-free) ----------
__device__ __half g_qh[BB * NSEQ * DQK];            // [b][i][d] hi
__device__ __half g_ql[BB * NSEQ * DQK];            // [b][i][d] lo
__device__ __half g_kh[BB * NSEQ * DQK];            // [b][j][d] hi
__device__ __half g_kl[BB * NSEQ * DQK];            // [b][j][d] lo
__device__ __half g_v [(size_t)BB * CC * NSEQ];     // [b][c][j] single fp16

__device__ __forceinline__ float ex2f(float x) {
    float r; asm("ex2.approx.f32 %0, %1;" : "=f"(r) : "f"(x)); return r;
}
__device__ __forceinline__ uint32_t smem_u32(const void* p) {
    uint32_t a;
    asm("{ .reg .u64 t; cvta.to.shared.u64 t, %1; cvt.u32.u64 %0, t; }" : "=r"(a) : "l"(p));
    return a;
}
__device__ __forceinline__ uint32_t pack_h2(float a, float b) {
    __half2 h = __floats2half2_rn(a, b);
    return *(uint32_t*)&h;
}
__device__ __forceinline__ uint32_t h2mul(uint32_t a, uint32_t b) {
    uint32_t r;
    asm("mul.rn.f16x2 %0, %1, %2;" : "=r"(r) : "r"(a), "r"(b));
    return r;
}
__device__ __forceinline__ void mma_f16(float* c, const uint32_t* a, uint32_t b0, uint32_t b1) {
    asm volatile("mma.sync.aligned.m16n8k16.row.col.f32.f16.f16.f32 "
        "{%0,%1,%2,%3}, {%4,%5,%6,%7}, {%8,%9}, {%0,%1,%2,%3};"
        : "+f"(c[0]), "+f"(c[1]), "+f"(c[2]), "+f"(c[3])
        : "r"(a[0]), "r"(a[1]), "r"(a[2]), "r"(a[3]), "r"(b0), "r"(b1));
}
__device__ __forceinline__ void ldsm4(uint32_t* r, uint32_t a) {
    asm volatile("ldmatrix.sync.aligned.m8n8.x4.shared.b16 {%0,%1,%2,%3}, [%4];"
        : "=r"(r[0]), "=r"(r[1]), "=r"(r[2]), "=r"(r[3]) : "r"(a));
}
__device__ __forceinline__ void cp16(uint32_t dst, const void* src) {
    asm volatile("cp.async.cg.shared.global [%0], [%1], 16;" :: "r"(dst), "l"(src));
}
#define CP_COMMIT() asm volatile("cp.async.commit_group;" ::: "memory")
#define CP_WAIT1()  asm volatile("cp.async.wait_group 1;" ::: "memory")
__device__ __forceinline__ void sts32(uint32_t a, uint32_t v) {
    asm volatile("st.shared.b32 [%0], %1;" :: "r"(a), "r"(v) : "memory");
}
__device__ __forceinline__ float lds32f(uint32_t a) {
    float v; asm volatile("ld.shared.f32 %0, [%1];" : "=f"(v) : "r"(a)); return v;
}
__device__ __forceinline__ void sts32f(uint32_t a, float v) {
    asm volatile("st.shared.f32 [%0], %1;" :: "r"(a), "f"(v) : "memory");
}

// ---------------- pass 1: QKV projection (SIMT fp32, 128x128 tile) ----------
// CTA: 128 o x 128 n, 256 thr, 8x8 micro in 4-wide quadrants.
// y == 0 -> o 0..127 = q|k (coalesced epilogue via hs staging) ; y>=1 -> v.
#define PW 140
#define PX 132

__global__ __launch_bounds__(256) void proj_kernel(
    const float* __restrict__ x,
    const float* __restrict__ wq, const float* __restrict__ bq,
    const float* __restrict__ wk, const float* __restrict__ bk,
    const float* __restrict__ wv, const float* __restrict__ bv)
{
    __shared__ float ws[16][PW];
    __shared__ float xs[16][PX];
    __shared__ __half hs[128][68];   // Q/K epilogue staging: [o][n-half]

    const int b  = blockIdx.z;
    const int o0 = blockIdx.y * 128;
    const int n0 = blockIdx.x * 128;
    const int t  = threadIdx.x;
    const int tx = t & 15;
    const int ty = t >> 4;

    const float* wptr[2];
    int wrow[2];
    const int wc4 = (t & 3) * 4;
#pragma unroll
    for (int r = 0; r < 2; r++) {
        int row = r * 64 + (t >> 2);
        wrow[r] = row;
        int o = o0 + row;
        const float* base;
        if (o < 64)        base = wq + (size_t)o * CC;
        else if (o < 128)  base = wk + (size_t)(o - 64) * CC;
        else               base = wv + (size_t)(o - 128) * CC;
        wptr[r] = base + wc4;
    }
    const int xn4 = (t & 31) * 4;
    const float* xptr[2];
    int xcr[2];
#pragma unroll
    for (int r = 0; r < 2; r++) {
        int c = r * 8 + (t >> 5);
        xcr[r] = c;
        xptr[r] = x + ((size_t)(b * CC) + c) * NSEQ + n0 + xn4;
    }

    float acc[8][8];
#pragma unroll
    for (int i = 0; i < 8; i++)
#pragma unroll
        for (int j = 0; j < 8; j++) acc[i][j] = 0.f;

    for (int c0 = 0; c0 < CC; c0 += 16) {
        float4 w4[2], x4[2];
#pragma unroll
        for (int r = 0; r < 2; r++) {
            w4[r] = *(const float4*)(wptr[r] + c0);
            x4[r] = *(const float4*)(xptr[r] + (size_t)c0 * NSEQ);
        }
        __syncthreads();
#pragma unroll
        for (int r = 0; r < 2; r++) {
            ws[wc4 + 0][wrow[r]] = w4[r].x;
            ws[wc4 + 1][wrow[r]] = w4[r].y;
            ws[wc4 + 2][wrow[r]] = w4[r].z;
            ws[wc4 + 3][wrow[r]] = w4[r].w;
            *(float4*)&xs[xcr[r]][xn4] = x4[r];
        }
        __syncthreads();
#pragma unroll
        for (int c = 0; c < 16; c++) {
            float4 a0 = *(const float4*)&ws[c][4 * ty];
            float4 a1 = *(const float4*)&ws[c][4 * ty + 64];
            float4 b0 = *(const float4*)&xs[c][4 * tx];
            float4 b1 = *(const float4*)&xs[c][4 * tx + 64];
            float av[8] = {a0.x, a0.y, a0.z, a0.w, a1.x, a1.y, a1.z, a1.w};
            float bv2[8] = {b0.x, b0.y, b0.z, b0.w, b1.x, b1.y, b1.z, b1.w};
#pragma unroll
            for (int i = 0; i < 8; i++)
#pragma unroll
                for (int j = 0; j < 8; j++)
                    acc[i][j] = fmaf(av[i], bv2[j], acc[i][j]);
        }
    }

    if (blockIdx.y == 0) {
        // Q/K epilogue: stage through hs, write coalesced [n][d] rows.
        // 4 rounds = (n-half h 0/1) x (pass hi/lo).
        const int nl_r = t & 63;          // reader: n within half
        const int sel  = (t >> 6) & 1;    // 0=q, 1=k
        const int kq   = t >> 7;          // d 32-half
#pragma unroll
        for (int h = 0; h < 2; h++) {
#pragma unroll
            for (int pass = 0; pass < 2; pass++) {
                __syncthreads();
#pragma unroll
                for (int i = 0; i < 8; i++) {
                    int o = 4 * ty + (i >> 2) * 64 + (i & 3);
                    int d = o & 63;
                    float bias = (o < 64) ? bq[d] : bk[d];
#pragma unroll
                    for (int jj = 0; jj < 4; jj++) {
                        int j = h * 4 + jj;           // (j>>2)==h
                        int nl = 4 * tx + (j & 3);
                        float v = acc[i][j] + bias;
                        __half hh = __float2half_rn(v);
                        if (pass) hh = __float2half_rn(v - __half2float(hh));
                        hs[o][nl] = hh;
                    }
                }
                __syncthreads();
                // coalesced write: thread -> (nl_r, sel, kq): 32 halves
                __half* dst;
                if (pass == 0) dst = sel ? g_kh : g_qh;
                else           dst = sel ? g_kl : g_ql;
                int n = n0 + h * 64 + nl_r;
                __half buf[32];
#pragma unroll
                for (int d = 0; d < 32; d++)
                    buf[d] = hs[sel * 64 + kq * 32 + d][nl_r];
                uint4* dp = (uint4*)(dst + ((size_t)(b * NSEQ) + n) * DQK + kq * 32);
#pragma unroll
                for (int k = 0; k < 4; k++)
                    dp[k] = ((uint4*)buf)[k];
            }
        }
    } else {
#pragma unroll
        for (int i = 0; i < 8; i++) {
            int c = (blockIdx.y - 1) * 128 + 4 * ty + (i >> 2) * 64 + (i & 3);
            float bias = bv[c];
#pragma unroll
            for (int k = 0; k < 2; k++) {
                int n = n0 + 4 * tx + k * 64;
                uint2 w2;
                w2.x = pack_h2(acc[i][4 * k + 0] + bias, acc[i][4 * k + 1] + bias);
                w2.y = pack_h2(acc[i][4 * k + 2] + bias, acc[i][4 * k + 3] + bias);
                *(uint2*)&g_v[((size_t)(b * CC + c)) * NSEQ + n] = w2;
            }
        }
    }
}

// ---------------- pass 2: HMMA flash attention, zero-redundancy GEMM1 -------
// CTA = 64 i x 512 c (FULL C), 8 warps = (ig 0..3) x (ch 0..1 j/c-half).
// Own-frame P store; cross-half correction on reloaded fp16 P via HMUL2.
#define KROW   144
#define S_Q    0                     /* Q hi 9216 | lo 9216 */
#define S_P    18432                 /* P: 64 x 144 = 9216 */
#define S_MX   27648                 /* chunk max (log2 units): 2 x 64 floats */
#define S_BUF  28160
#define SK_H   0
#define SK_L   9216
#define SV     18432
#define TILE_BYTES 92160             /* K 2x9216 + V 512x144 */
#define N_CHUNK (NSEQ / 64)
#define STG_ROW 68
#define OUT_SMEM_BYTES (S_BUF + 2 * TILE_BYTES)   /* 212480 */

__device__ __forceinline__ void issue_tiles(uint32_t tb, int b, int j0, int t)
{
#pragma unroll
    for (int r = 0; r < 4; r++) {           // K hi+lo: 1024 16B chunks
        int idx = t + r * 256;
        int arr = idx >> 9;
        int row = (idx >> 3) & 63;
        int col = idx & 7;
        const __half* src = (arr ? g_kl : g_kh) + ((size_t)b * NSEQ + j0 + row) * DQK + col * 8;
        cp16(tb + SK_H + arr * 9216 + row * KROW + col * 16, src);
    }
#pragma unroll
    for (int r = 0; r < 16; r++) {          // V: 4096 16B chunks (512 c rows)
        int idx = t + r * 256;
        int row = (idx >> 3) & 511;
        int col = idx & 7;
        const __half* src = g_v + ((size_t)(b * CC) + row) * NSEQ + j0 + col * 8;
        cp16(tb + SV + row * KROW + col * 16, src);
    }
}

__global__ __launch_bounds__(256, 1) void out_kernel(float* __restrict__ out)
{
    extern __shared__ char smem[];
    const uint32_t sb = smem_u32(smem);
    const int b  = blockIdx.z;
    const int i0 = blockIdx.x * 64;
    const int t  = threadIdx.x;
    const int w  = t >> 5;
    const int lane = t & 31;
    const int g  = lane >> 2;
    const int t4 = lane & 3;
    const int l8 = lane & 7;
    const int tt = lane >> 3;
    const int ig = w & 3;        // i-group (16 rows)
    const int ch = w >> 2;       // j-half (GEMM1) == c-half (GEMM2)

    // stage Q hi/lo [64 i][64 d]
#pragma unroll
    for (int r = 0; r < 4; r++) {
        int idx = t + r * 256;
        int arr = idx >> 9;
        int row = (idx >> 3) & 63;
        int col = idx & 7;
        const __half* src = (arr ? g_ql : g_qh) + ((size_t)b * NSEQ + i0 + row) * DQK + col * 8;
        cp16(sb + S_Q + arr * 9216 + row * KROW + col * 16, src);
    }
    issue_tiles(sb + S_BUF, b, 0, t);
    CP_COMMIT();

    const uint32_t frow = (uint32_t)(ig * 16 + l8 + ((lane >> 3) & 1) * 8) * KROW
                        + (uint32_t)((lane >> 4) * 16);
    const uint32_t qlrow = sb + S_Q + frow;
    const uint32_t prow  = sb + S_P + frow;
    const uint32_t psts0 = sb + S_P + (uint32_t)(ig * 16 + g) * KROW + (uint32_t)(ch * 64 + 4 * t4);
    const uint32_t psts1 = psts0 + 8 * KROW;
    const uint32_t mrow0 = sb + S_MX + (uint32_t)(ig * 16 + g) * 4;

    float o[32][4];
#pragma unroll
    for (int ct = 0; ct < 32; ct++)
#pragma unroll
        for (int r = 0; r < 4; r++) o[ct][r] = 0.f;
    float la[4] = {0.f, 0.f, 0.f, 0.f};
    float m0 = -1e30f, m1 = -1e30f;
    const uint32_t ONE2 = 0x3C003C00u;

    for (int it = 0; it < N_CHUNK; ++it) {
        if (it + 1 < N_CHUNK)
            issue_tiles(sb + S_BUF + ((it + 1) & 1) * TILE_BYTES, b, (it + 1) * 64, t);
        CP_COMMIT();
        CP_WAIT1();
        __syncthreads();

        const uint32_t tb = sb + S_BUF + (it & 1) * TILE_BYTES;

        // ---- GEMM1: S = Q K^T for 16i x 32j (split-3 fp16) ----
        float s[4][4];
#pragma unroll
        for (int q = 0; q < 4; q++)
#pragma unroll
            for (int r = 0; r < 4; r++) s[q][r] = 0.f;

#pragma unroll
        for (int kp = 0; kp < 2; kp++) {
            uint32_t qh0[4], qh1[4], ql0[4], ql1[4];
            uint32_t qcol = (uint32_t)(kp * 64);
            ldsm4(qh0, qlrow + qcol);
            ldsm4(qh1, qlrow + qcol + 32);
            ldsm4(ql0, qlrow + 9216 + qcol);
            ldsm4(ql1, qlrow + 9216 + qcol + 32);
#pragma unroll
            for (int q = 0; q < 4; q++) {
                int nt = ch * 4 + q;
                uint32_t krow = tb + (nt * 8 + l8) * KROW + tt * 16;
                uint32_t kh[4], kl[4];
                ldsm4(kh, krow + SK_H + kp * 64);
                ldsm4(kl, krow + SK_L + kp * 64);
                mma_f16(s[q], qh0, kh[0], kh[1]);
                mma_f16(s[q], qh1, kh[2], kh[3]);
                mma_f16(s[q], ql0, kh[0], kh[1]);
                mma_f16(s[q], ql1, kh[2], kh[3]);
                mma_f16(s[q], qh0, kl[0], kl[1]);
                mma_f16(s[q], qh1, kl[2], kl[3]);
            }
        }

        // ---- own-half row chunk-max (log2 units) ----
        float cm0 = -1e30f, cm1 = -1e30f;
#pragma unroll
        for (int q = 0; q < 4; q++) {
            cm0 = fmaxf(cm0, fmaxf(s[q][0], s[q][1]));
            cm1 = fmaxf(cm1, fmaxf(s[q][2], s[q][3]));
        }
        cm0 = fmaxf(cm0, __shfl_xor_sync(0xFFFFFFFFu, cm0, 1));
        cm0 = fmaxf(cm0, __shfl_xor_sync(0xFFFFFFFFu, cm0, 2));
        cm1 = fmaxf(cm1, __shfl_xor_sync(0xFFFFFFFFu, cm1, 1));
        cm1 = fmaxf(cm1, __shfl_xor_sync(0xFFFFFFFFu, cm1, 2));
        const float cmL0 = cm0 * LOG2E;
        const float cmL1 = cm1 * LOG2E;
        if (t4 == 0) {
            sts32f(mrow0 + (uint32_t)(ch * 256), cmL0);
            sts32f(mrow0 + (uint32_t)(ch * 256) + 32, cmL1);
        }

        // ---- exp in OWN-chunk frame + STS fp16 P (before the sync) ----
#pragma unroll
        for (int kt = 0; kt < 2; kt++) {
            float pg0 = ex2f(fmaf(s[2 * kt][0],     LOG2E, -cmL0));
            float pg1 = ex2f(fmaf(s[2 * kt][1],     LOG2E, -cmL0));
            float pg2 = ex2f(fmaf(s[2 * kt + 1][0], LOG2E, -cmL0));
            float pg3 = ex2f(fmaf(s[2 * kt + 1][1], LOG2E, -cmL0));
            float ph0 = ex2f(fmaf(s[2 * kt][2],     LOG2E, -cmL1));
            float ph1 = ex2f(fmaf(s[2 * kt][3],     LOG2E, -cmL1));
            float ph2 = ex2f(fmaf(s[2 * kt + 1][2], LOG2E, -cmL1));
            float ph3 = ex2f(fmaf(s[2 * kt + 1][3], LOG2E, -cmL1));
            sts32(psts0 + kt * 32,      pack_h2(pg0, pg1));
            sts32(psts0 + kt * 32 + 16, pack_h2(pg2, pg3));
            sts32(psts1 + kt * 32,      pack_h2(ph0, ph1));
            sts32(psts1 + kt * 32 + 16, pack_h2(ph2, ph3));
        }
        __syncthreads();

        // ---- global frame update + correction factors ----
        const float h0r0 = lds32f(mrow0);
        const float h1r0 = lds32f(mrow0 + 256);
        const float h0r1 = lds32f(mrow0 + 32);
        const float h1r1 = lds32f(mrow0 + 32 + 256);
        float m0n = fmaxf(m0, fmaxf(h0r0, h1r0));
        float m1n = fmaxf(m1, fmaxf(h0r1, h1r1));
        float f0 = ex2f(m0 - m0n);
        float f1 = ex2f(m1 - m1n);
        m0 = m0n; m1 = m1n;
        la[0] *= f0; la[1] *= f0; la[2] *= f1; la[3] *= f1;
        if (__any_sync(0xFFFFFFFFu, fminf(f0, f1) < 0.9999995f)) {
#pragma unroll
            for (int ct = 0; ct < 32; ct++) {
                o[ct][0] *= f0; o[ct][1] *= f0;
                o[ct][2] *= f1; o[ct][3] *= f1;
            }
        }
        const uint32_t c0r0 = pack_h2(ex2f(h0r0 - m0n), ex2f(h0r0 - m0n));
        const uint32_t c1r0 = pack_h2(ex2f(h1r0 - m0n), ex2f(h1r0 - m0n));
        const uint32_t c0r1 = pack_h2(ex2f(h0r1 - m1n), ex2f(h0r1 - m1n));
        const uint32_t c1r1 = pack_h2(ex2f(h1r1 - m1n), ex2f(h1r1 - m1n));

        // ---- load full-row P fragments, correct to global frame ----
        uint32_t pa[4][4];
#pragma unroll
        for (int kt = 0; kt < 4; kt++)
            ldsm4(pa[kt], prow + kt * 32);
#pragma unroll
        for (int kt = 0; kt < 4; kt++) {
            const uint32_t cr0 = (kt >> 1) ? c1r0 : c0r0;
            const uint32_t cr1 = (kt >> 1) ? c1r1 : c0r1;
            pa[kt][0] = h2mul(pa[kt][0], cr0);
            pa[kt][1] = h2mul(pa[kt][1], cr1);
            pa[kt][2] = h2mul(pa[kt][2], cr0);
            pa[kt][3] = h2mul(pa[kt][3], cr1);
        }

        // ---- row sums via ones-MMA ----
#pragma unroll
        for (int kt = 0; kt < 4; kt++)
            mma_f16(la, pa[kt], ONE2, ONE2);

        // ---- GEMM2: o += P V^T, warp tile 16i x 256c ----
#pragma unroll
        for (int ct = 0; ct < 32; ct++) {
            uint32_t vrow = tb + SV + (ch * 256 + ct * 8 + l8) * KROW + tt * 16;
#pragma unroll
            for (int jh = 0; jh < 2; jh++) {
                uint32_t vv[4];
                ldsm4(vv, vrow + jh * 64);
                mma_f16(o[ct], pa[2 * jh],     vv[0], vv[1]);
                mma_f16(o[ct], pa[2 * jh + 1], vv[2], vv[3]);
            }
        }
        __syncthreads();
    }

    const float li0 = 1.0f / la[0];
    const float li1 = 1.0f / la[2];

    // epilogue: scale, transpose through SMEM staging (512c x 64i), store
    float* stg = (float*)smem;
    const int il = ig * 16 + g;
#pragma unroll
    for (int ct = 0; ct < 32; ct++) {
        int c = ch * 256 + ct * 8 + 2 * t4;
        stg[(size_t)c * STG_ROW + il]           = o[ct][0] * li0;
        stg[(size_t)(c + 1) * STG_ROW + il]     = o[ct][1] * li0;
        stg[(size_t)c * STG_ROW + il + 8]       = o[ct][2] * li1;
        stg[(size_t)(c + 1) * STG_ROW + il + 8] = o[ct][3] * li1;
    }
    __syncthreads();
#pragma unroll
    for (int r = 0; r < 32; r++) {
        int fid = t + r * 256;               // 8192 float4 = 512c x 16
        int c = fid >> 4, x = fid & 15;
        float4 v = *(const float4*)&stg[(size_t)c * STG_ROW + x * 4];
        *(float4*)(out + ((size_t)(b * CC + c)) * NSEQ + i0 + x * 4) = v;
    }
}

// ---------------- launch ----------------------------------------------------
extern "C" void kernel_launch(void* const* d_in, const int* in_sizes, int n_in,
                              void* d_out, int out_size)
{
    const float* x  = (const float*)d_in[0];
    const float* wq = (const float*)d_in[1];
    const float* bq = (const float*)d_in[2];
    const float* wk = (const float*)d_in[3];
    const float* bk = (const float*)d_in[4];
    const float* wv = (const float*)d_in[5];
    const float* bv = (const float*)d_in[6];
    float* out = (float*)d_out;

    proj_kernel<<<dim3(NSEQ / 128, 5, BB), 256>>>(x, wq, bq, wk, bk, wv, bv);
    cudaFuncSetAttribute(out_kernel, cudaFuncAttributeMaxDynamicSharedMemorySize, OUT_SMEM_BYTES);
    out_kernel<<<dim3(NSEQ / 64, 1, BB), 256, OUT_SMEM_BYTES>>>(out);
}